// round 2
// baseline (speedup 1.0000x reference)
#include <cuda_runtime.h>
#include <cuda_bf16.h>
#include <cstdint>

// Problem constants (fixed-shape problem)
#define HIDDEN   128
#define N_NODES  1000000
#define N_GRAPHS 4096

#define ROWS_PER_WARP 64
#define N_WARPSPANS   (N_NODES / ROWS_PER_WARP)   // 15625 exactly
#define POOL_THREADS  256
#define POOL_BLOCKS   ((N_WARPSPANS + (POOL_THREADS/32) - 1) / (POOL_THREADS/32)) // 1954

// Scratch (no cudaMalloc allowed)
__device__ float    g_sums[N_GRAPHS * HIDDEN];
__device__ unsigned g_maxs[N_GRAPHS * HIDDEN];   // ordered-uint encoded floats
__device__ int      g_counts[N_GRAPHS];
__device__ int      g_is64;                      // batch dtype flag

// ---- ordered-uint float encoding (monotone; supports atomicMax) ----
__device__ __forceinline__ unsigned ordf(float f) {
    unsigned u = __float_as_uint(f);
    return (u & 0x80000000u) ? ~u : (u | 0x80000000u);
}
__device__ __forceinline__ float unordf(unsigned u) {
    return __uint_as_float((u & 0x80000000u) ? (u ^ 0x80000000u) : ~u);
}
// ordf(-inf) = ~0xFF800000 = 0x007FFFFF
#define ORD_NEG_INF 0x007FFFFFu

// ------------------------------------------------------------------
// Kernel -1: detect batch dtype. Sorted ids in [0,4096) mean an int64
// element's high word is always 0; the int32 interpretation puts real
// (mostly nonzero) ids at those byte offsets. Reads stay within the
// smaller (int32) allocation: int2 index < N_NODES/2.
// ------------------------------------------------------------------
__global__ void detect_kernel(const int2* __restrict__ b2) {
    int nonzero_hi = 0;
    #pragma unroll
    for (int k = 1; k <= 8; k++) {
        nonzero_hi |= b2[N_NODES / 2 - k].y;
        nonzero_hi |= b2[N_NODES / 4 + k].y;
    }
    g_is64 = (nonzero_hi == 0) ? 1 : 0;
}

// ------------------------------------------------------------------
// Kernel 0: init scratch
// ------------------------------------------------------------------
__global__ void init_kernel() {
    int i = blockIdx.x * blockDim.x + threadIdx.x;
    if (i < N_GRAPHS * HIDDEN) {
        g_sums[i] = 0.0f;
        g_maxs[i] = ORD_NEG_INF;
    }
    if (i < N_GRAPHS) g_counts[i] = 0;
}

// ------------------------------------------------------------------
// Kernel 1: pooling pass. Exploits sorted batch: per-warp contiguous
// 64-row span, register accumulation, atomic flush only on segment
// boundaries. Lane l owns columns 4l..4l+3 (float4).
// ------------------------------------------------------------------
__device__ __forceinline__ void flush_seg(int g, float4 a, float4 m, int n, int lane) {
    if ((unsigned)g >= N_GRAPHS) return;   // safety: never trap on bad ids
    float*    sp = &g_sums[g * HIDDEN + 4 * lane];
    unsigned* mp = &g_maxs[g * HIDDEN + 4 * lane];
    atomicAdd(sp + 0, a.x);
    atomicAdd(sp + 1, a.y);
    atomicAdd(sp + 2, a.z);
    atomicAdd(sp + 3, a.w);
    atomicMax(mp + 0, ordf(m.x));
    atomicMax(mp + 1, ordf(m.y));
    atomicMax(mp + 2, ordf(m.z));
    atomicMax(mp + 3, ordf(m.w));
    if (lane == 0) atomicAdd(&g_counts[g], n);
}

template <typename IT>
__device__ __forceinline__ void pool_span(const float4* __restrict__ x4,
                                          const IT* __restrict__ batch,
                                          int row0, int lane) {
    const float NEG_INF = -__int_as_float(0x7F800000); // -inf
    float4 acc = make_float4(0.f, 0.f, 0.f, 0.f);
    float4 mx  = make_float4(NEG_INF, NEG_INF, NEG_INF, NEG_INF);
    int cur = -1, seglen = 0;

    for (int mb = 0; mb < ROWS_PER_WARP / 8; mb++) {
        int base = row0 + mb * 8;
        int    bb[8];
        float4 vv[8];
        // Phase 1: batch all loads (MLP)
        #pragma unroll
        for (int i = 0; i < 8; i++) {
            bb[i] = (int)batch[base + i];
            vv[i] = x4[(size_t)(base + i) * (HIDDEN / 4) + lane];
        }
        // Phase 2: accumulate, flushing on segment change
        #pragma unroll
        for (int i = 0; i < 8; i++) {
            int g = bb[i];
            if (g != cur) {
                if (cur >= 0) flush_seg(cur, acc, mx, seglen, lane);
                cur = g;
                acc = make_float4(0.f, 0.f, 0.f, 0.f);
                mx  = make_float4(NEG_INF, NEG_INF, NEG_INF, NEG_INF);
                seglen = 0;
            }
            acc.x += vv[i].x; acc.y += vv[i].y; acc.z += vv[i].z; acc.w += vv[i].w;
            mx.x = fmaxf(mx.x, vv[i].x); mx.y = fmaxf(mx.y, vv[i].y);
            mx.z = fmaxf(mx.z, vv[i].z); mx.w = fmaxf(mx.w, vv[i].w);
            seglen++;
        }
    }
    flush_seg(cur, acc, mx, seglen, lane);
}

__global__ __launch_bounds__(POOL_THREADS)
void pool_kernel(const float4* __restrict__ x4, const void* __restrict__ batch) {
    int wg   = (blockIdx.x * blockDim.x + threadIdx.x) >> 5;  // global warp-span id
    int lane = threadIdx.x & 31;
    if (wg >= N_WARPSPANS) return;
    int row0 = wg * ROWS_PER_WARP;

    if (g_is64) pool_span<long long>(x4, (const long long*)batch, row0, lane);
    else        pool_span<int>(x4, (const int*)batch, row0, lane);
}

// ------------------------------------------------------------------
// Kernel 2: epilogue. Per block: 16 graphs. pooled[G,384] @ W[384,128]
// + b, LayerNorm, exact GELU. W tiled 64x128 through static smem,
// 6 k-tiles. Warp w owns graphs 2w,2w+1; lane l owns cols 4l..4l+3.
// ------------------------------------------------------------------
#define GPB 16
#define KT  64

__global__ __launch_bounds__(256)
void epilogue_kernel(const float* __restrict__ W, const float* __restrict__ bias,
                     const float* __restrict__ gamma, const float* __restrict__ beta,
                     float* __restrict__ out) {
    __shared__ float Ws[KT * HIDDEN];   // 32 KB
    __shared__ float Ps[GPB][KT];       // 4 KB
    __shared__ float s_inv[GPB];
    __shared__ float s_cnt[GPB];

    int g0  = blockIdx.x * GPB;
    int tid = threadIdx.x;            // 256
    int warp = tid >> 5, lane = tid & 31;

    if (tid < GPB) {
        int c = g_counts[g0 + tid];
        s_cnt[tid] = (float)c;
        s_inv[tid] = 1.0f / fmaxf((float)c, 1.0f);
    }
    __syncthreads();

    float acc[2][4] = {{0.f,0.f,0.f,0.f},{0.f,0.f,0.f,0.f}};
    int gl0 = 2 * warp;

    for (int kt = 0; kt < 3 * HIDDEN / KT; kt++) {   // 6 tiles
        // load W tile (rows kt*64..+64, all 128 cols): 8192 floats
        const float4* Wg  = (const float4*)(W + kt * KT * HIDDEN);
        float4*       Wsv = (float4*)Ws;
        #pragma unroll
        for (int i = 0; i < 8; i++) Wsv[tid + i * 256] = Wg[tid + i * 256];

        // build pooled tile: section uniform per tile
        int section = kt >> 1;               // 0=mean 1=max 2=sum
        int colbase = (kt & 1) * KT;
        #pragma unroll
        for (int i = 0; i < 4; i++) {
            int idx = tid + i * 256;         // 0..1023
            int gl  = idx >> 6;              // 0..15
            int j   = idx & 63;
            int gg  = g0 + gl;
            int col = colbase + j;
            float v;
            if (section == 0)      v = g_sums[gg * HIDDEN + col] * s_inv[gl];
            else if (section == 1) v = (s_cnt[gl] > 0.f) ? unordf(g_maxs[gg * HIDDEN + col]) : 0.f;
            else                   v = g_sums[gg * HIDDEN + col];
            Ps[gl][j] = v;
        }
        __syncthreads();

        #pragma unroll 8
        for (int k = 0; k < KT; k++) {
            float4 w  = ((const float4*)(Ws + k * HIDDEN))[lane];
            float  p0 = Ps[gl0][k];
            float  p1 = Ps[gl0 + 1][k];
            acc[0][0] += p0 * w.x; acc[0][1] += p0 * w.y;
            acc[0][2] += p0 * w.z; acc[0][3] += p0 * w.w;
            acc[1][0] += p1 * w.x; acc[1][1] += p1 * w.y;
            acc[1][2] += p1 * w.z; acc[1][3] += p1 * w.w;
        }
        __syncthreads();
    }

    // bias + LayerNorm + exact GELU
    float4 b4 = ((const float4*)bias)[lane];
    float4 gm = ((const float4*)gamma)[lane];
    float4 bt = ((const float4*)beta)[lane];
    const float eps = 1e-5f;

    #pragma unroll
    for (int gi = 0; gi < 2; gi++) {
        int g = g0 + gl0 + gi;
        float h[4];
        h[0] = acc[gi][0] + b4.x; h[1] = acc[gi][1] + b4.y;
        h[2] = acc[gi][2] + b4.z; h[3] = acc[gi][3] + b4.w;

        float s = h[0] + h[1] + h[2] + h[3];
        #pragma unroll
        for (int o = 16; o; o >>= 1) s += __shfl_xor_sync(0xFFFFFFFFu, s, o);
        float mu = s * (1.0f / 128.0f);

        float d0 = h[0]-mu, d1 = h[1]-mu, d2 = h[2]-mu, d3 = h[3]-mu;
        float v = d0*d0 + d1*d1 + d2*d2 + d3*d3;
        #pragma unroll
        for (int o = 16; o; o >>= 1) v += __shfl_xor_sync(0xFFFFFFFFu, v, o);
        float rstd = rsqrtf(v * (1.0f / 128.0f) + eps);

        float gmv[4] = {gm.x, gm.y, gm.z, gm.w};
        float btv[4] = {bt.x, bt.y, bt.z, bt.w};
        #pragma unroll
        for (int k = 0; k < 4; k++) {
            float t = (h[k] - mu) * rstd * gmv[k] + btv[k];
            float ge = 0.5f * t * (1.0f + erff(t * 0.70710678118654752f));
            out[(size_t)g * HIDDEN + 4 * lane + k] = ge;
        }
    }
}

// ------------------------------------------------------------------
extern "C" void kernel_launch(void* const* d_in, const int* in_sizes, int n_in,
                              void* d_out, int out_size) {
    const float* x     = nullptr;
    const void*  batch = nullptr;
    const float* W     = nullptr;
    const float* b     = nullptr;
    const float* gamma = nullptr;
    const float* beta  = nullptr;

    for (int i = 0; i < n_in; i++) {
        int s = in_sizes[i];
        if (s == N_NODES * HIDDEN)         x = (const float*)d_in[i];
        else if (s == N_NODES)             batch = d_in[i];
        else if (s == 3 * HIDDEN * HIDDEN) W = (const float*)d_in[i];
        else if (s == HIDDEN) {
            if (!b) b = (const float*)d_in[i];
            else if (!gamma) gamma = (const float*)d_in[i];
            else if (!beta)  beta = (const float*)d_in[i];
        }
        // size-1 num_graphs scalar (if present) is ignored: hardcoded 4096
    }

    // dtype detection + scratch init
    detect_kernel<<<1, 1>>>((const int2*)batch);
    {
        int total = N_GRAPHS * HIDDEN;
        int thr = 256;
        init_kernel<<<(total + thr - 1) / thr, thr>>>();
    }
    // pooling
    pool_kernel<<<POOL_BLOCKS, POOL_THREADS>>>((const float4*)x, batch);
    // epilogue
    epilogue_kernel<<<N_GRAPHS / GPB, 256>>>(W, b, gamma, beta, (float*)d_out);
}

// round 3
// speedup vs baseline: 1.0789x; 1.0789x over previous
#include <cuda_runtime.h>
#include <cuda_bf16.h>
#include <cstdint>

// Problem constants (fixed-shape problem)
#define HIDDEN   128
#define N_NODES  1000000
#define N_GRAPHS 4096

#define ROWS_PER_WARP 64
#define N_WARPSPANS   (N_NODES / ROWS_PER_WARP)   // 15625 exactly
#define POOL_THREADS  256
#define POOL_BLOCKS   ((N_WARPSPANS + (POOL_THREADS/32) - 1) / (POOL_THREADS/32)) // 1954

// Scratch (no cudaMalloc allowed)
__device__ float    g_sums[N_GRAPHS * HIDDEN];
__device__ unsigned g_maxs[N_GRAPHS * HIDDEN];   // ordered-uint encoded floats
__device__ int      g_counts[N_GRAPHS];
__device__ int      g_is64;                      // batch dtype flag

// ---- ordered-uint float encoding (monotone; supports atomicMax) ----
__device__ __forceinline__ unsigned ordf(float f) {
    unsigned u = __float_as_uint(f);
    return (u & 0x80000000u) ? ~u : (u | 0x80000000u);
}
__device__ __forceinline__ float unordf(unsigned u) {
    return __uint_as_float((u & 0x80000000u) ? (u ^ 0x80000000u) : ~u);
}
#define ORD_NEG_INF 0x007FFFFFu

// ------------------------------------------------------------------
// Kernel -1: detect batch dtype (int32 vs int64). Sorted ids in
// [0,4096): int64 elements always have zero high words.
// ------------------------------------------------------------------
__global__ void detect_kernel(const int2* __restrict__ b2) {
    int nonzero_hi = 0;
    #pragma unroll
    for (int k = 1; k <= 8; k++) {
        nonzero_hi |= b2[N_NODES / 2 - k].y;
        nonzero_hi |= b2[N_NODES / 4 + k].y;
    }
    g_is64 = (nonzero_hi == 0) ? 1 : 0;
}

// ------------------------------------------------------------------
// Kernel 0: init scratch
// ------------------------------------------------------------------
__global__ void init_kernel() {
    int i = blockIdx.x * blockDim.x + threadIdx.x;
    if (i < N_GRAPHS * HIDDEN) {
        g_sums[i] = 0.0f;
        g_maxs[i] = ORD_NEG_INF;
    }
    if (i < N_GRAPHS) g_counts[i] = 0;
}

// ------------------------------------------------------------------
// Kernel 1: pooling. Per-warp contiguous 64-row span, register
// accumulation, atomic flush on segment boundaries only.
// ------------------------------------------------------------------
__device__ __forceinline__ void flush_seg(int g, float4 a, float4 m, int n, int lane) {
    if ((unsigned)g >= N_GRAPHS) return;
    float*    sp = &g_sums[g * HIDDEN + 4 * lane];
    unsigned* mp = &g_maxs[g * HIDDEN + 4 * lane];
    atomicAdd(sp + 0, a.x);
    atomicAdd(sp + 1, a.y);
    atomicAdd(sp + 2, a.z);
    atomicAdd(sp + 3, a.w);
    atomicMax(mp + 0, ordf(m.x));
    atomicMax(mp + 1, ordf(m.y));
    atomicMax(mp + 2, ordf(m.z));
    atomicMax(mp + 3, ordf(m.w));
    if (lane == 0) atomicAdd(&g_counts[g], n);
}

template <typename IT>
__device__ __forceinline__ void pool_span(const float4* __restrict__ x4,
                                          const IT* __restrict__ batch,
                                          int row0, int lane) {
    const float NEG_INF = -__int_as_float(0x7F800000); // -inf
    float4 acc = make_float4(0.f, 0.f, 0.f, 0.f);
    float4 mx  = make_float4(NEG_INF, NEG_INF, NEG_INF, NEG_INF);
    int cur = -1, seglen = 0;

    for (int mb = 0; mb < ROWS_PER_WARP / 8; mb++) {
        int base = row0 + mb * 8;
        int    bb[8];
        float4 vv[8];
        // Phase 1: batch all loads (MLP). x is streamed once -> evict-first.
        #pragma unroll
        for (int i = 0; i < 8; i++) {
            bb[i] = (int)batch[base + i];
            vv[i] = __ldcs(&x4[(size_t)(base + i) * (HIDDEN / 4) + lane]);
        }
        // Phase 2: accumulate, flushing on segment change
        #pragma unroll
        for (int i = 0; i < 8; i++) {
            int g = bb[i];
            if (g != cur) {
                if (cur >= 0) flush_seg(cur, acc, mx, seglen, lane);
                cur = g;
                acc = make_float4(0.f, 0.f, 0.f, 0.f);
                mx  = make_float4(NEG_INF, NEG_INF, NEG_INF, NEG_INF);
                seglen = 0;
            }
            acc.x += vv[i].x; acc.y += vv[i].y; acc.z += vv[i].z; acc.w += vv[i].w;
            mx.x = fmaxf(mx.x, vv[i].x); mx.y = fmaxf(mx.y, vv[i].y);
            mx.z = fmaxf(mx.z, vv[i].z); mx.w = fmaxf(mx.w, vv[i].w);
            seglen++;
        }
    }
    flush_seg(cur, acc, mx, seglen, lane);
}

__global__ __launch_bounds__(POOL_THREADS)
void pool_kernel(const float4* __restrict__ x4, const void* __restrict__ batch) {
    int wg   = (blockIdx.x * blockDim.x + threadIdx.x) >> 5;
    int lane = threadIdx.x & 31;
    if (wg >= N_WARPSPANS) return;
    int row0 = wg * ROWS_PER_WARP;

    if (g_is64) pool_span<long long>(x4, (const long long*)batch, row0, lane);
    else        pool_span<int>(x4, (const int*)batch, row0, lane);
}

// ------------------------------------------------------------------
// Kernel 2: epilogue. 256 blocks x 128 threads; block = 16 graphs;
// warp = 4 graphs; lane = 4 output cols. f32x2 packed FMA; pooled
// values read float4-per-4k to cut broadcast LDS 4x.
// ------------------------------------------------------------------
#define GPB 16
#define KT  64

__device__ __forceinline__ void ffma2(unsigned long long& acc,
                                      unsigned long long w2,
                                      unsigned long long p2) {
    asm("fma.rn.f32x2 %0, %1, %2, %0;" : "+l"(acc) : "l"(w2), "l"(p2));
}
__device__ __forceinline__ unsigned long long pack2(float p) {
    unsigned long long r;
    asm("mov.b64 %0, {%1, %1};" : "=l"(r) : "r"(__float_as_uint(p)));
    return r;
}

__global__ __launch_bounds__(128)
void epilogue_kernel(const float* __restrict__ W, const float* __restrict__ bias,
                     const float* __restrict__ gamma, const float* __restrict__ beta,
                     float* __restrict__ out) {
    __shared__ float Ws[KT * HIDDEN];   // 32 KB
    __shared__ float Ps[GPB][KT];       // 4 KB
    __shared__ float s_inv[GPB];
    __shared__ float s_cnt[GPB];

    int g0  = blockIdx.x * GPB;
    int tid = threadIdx.x;            // 128
    int warp = tid >> 5, lane = tid & 31;

    if (tid < GPB) {
        int c = g_counts[g0 + tid];
        s_cnt[tid] = (float)c;
        s_inv[tid] = 1.0f / fmaxf((float)c, 1.0f);
    }
    __syncthreads();

    unsigned long long acc2[4][2] = {{0ull,0ull},{0ull,0ull},{0ull,0ull},{0ull,0ull}};
    int gl0 = 4 * warp;               // warp owns graphs gl0..gl0+3

    #pragma unroll 1
    for (int kt = 0; kt < 3 * HIDDEN / KT; kt++) {   // 6 tiles
        // load W tile (KT x 128 = 8192 floats = 2048 float4, 128 threads)
        const float4* Wg  = (const float4*)(W + kt * KT * HIDDEN);
        float4*       Wsv = (float4*)Ws;
        #pragma unroll
        for (int i = 0; i < 16; i++) Wsv[tid + i * 128] = Wg[tid + i * 128];

        // build pooled tile (GPB*KT = 1024 floats, 8 per thread)
        int section = kt >> 1;               // 0=mean 1=max 2=sum
        int colbase = (kt & 1) * KT;
        #pragma unroll
        for (int i = 0; i < 8; i++) {
            int idx = tid + i * 128;         // 0..1023
            int gl  = idx >> 6;              // 0..15
            int j   = idx & 63;
            int gg  = g0 + gl;
            int col = colbase + j;
            float v;
            if (section == 0)      v = g_sums[gg * HIDDEN + col] * s_inv[gl];
            else if (section == 1) v = (s_cnt[gl] > 0.f) ? unordf(g_maxs[gg * HIDDEN + col]) : 0.f;
            else                   v = g_sums[gg * HIDDEN + col];
            Ps[gl][j] = v;
        }
        __syncthreads();

        #pragma unroll 4
        for (int k4 = 0; k4 < KT / 4; k4++) {
            float4 pv[4];
            #pragma unroll
            for (int g = 0; g < 4; g++)
                pv[g] = ((const float4*)Ps[gl0 + g])[k4];   // broadcast LDS.128
            #pragma unroll
            for (int kk = 0; kk < 4; kk++) {
                int k = k4 * 4 + kk;
                ulonglong2 w2 = ((const ulonglong2*)(Ws + k * HIDDEN))[lane];
                #pragma unroll
                for (int g = 0; g < 4; g++) {
                    float p = (kk == 0) ? pv[g].x : (kk == 1) ? pv[g].y
                            : (kk == 2) ? pv[g].z : pv[g].w;
                    unsigned long long p2 = pack2(p);
                    ffma2(acc2[g][0], w2.x, p2);
                    ffma2(acc2[g][1], w2.y, p2);
                }
            }
        }
        __syncthreads();
    }

    // bias + LayerNorm + exact GELU (4 graphs per warp)
    float4 b4 = ((const float4*)bias)[lane];
    float4 gm = ((const float4*)gamma)[lane];
    float4 bt = ((const float4*)beta)[lane];
    const float eps = 1e-5f;

    #pragma unroll
    for (int gi = 0; gi < 4; gi++) {
        int g = g0 + gl0 + gi;
        unsigned lo0, hi0, lo1, hi1;
        asm("mov.b64 {%0, %1}, %2;" : "=r"(lo0), "=r"(hi0) : "l"(acc2[gi][0]));
        asm("mov.b64 {%0, %1}, %2;" : "=r"(lo1), "=r"(hi1) : "l"(acc2[gi][1]));
        float h[4];
        h[0] = __uint_as_float(lo0) + b4.x;
        h[1] = __uint_as_float(hi0) + b4.y;
        h[2] = __uint_as_float(lo1) + b4.z;
        h[3] = __uint_as_float(hi1) + b4.w;

        float s = h[0] + h[1] + h[2] + h[3];
        #pragma unroll
        for (int o = 16; o; o >>= 1) s += __shfl_xor_sync(0xFFFFFFFFu, s, o);
        float mu = s * (1.0f / 128.0f);

        float d0 = h[0]-mu, d1 = h[1]-mu, d2 = h[2]-mu, d3 = h[3]-mu;
        float v = d0*d0 + d1*d1 + d2*d2 + d3*d3;
        #pragma unroll
        for (int o = 16; o; o >>= 1) v += __shfl_xor_sync(0xFFFFFFFFu, v, o);
        float rstd = rsqrtf(v * (1.0f / 128.0f) + eps);

        float gmv[4] = {gm.x, gm.y, gm.z, gm.w};
        float btv[4] = {bt.x, bt.y, bt.z, bt.w};
        #pragma unroll
        for (int k = 0; k < 4; k++) {
            float t = (h[k] - mu) * rstd * gmv[k] + btv[k];
            float ge = 0.5f * t * (1.0f + erff(t * 0.70710678118654752f));
            out[(size_t)g * HIDDEN + 4 * lane + k] = ge;
        }
    }
}

// ------------------------------------------------------------------
extern "C" void kernel_launch(void* const* d_in, const int* in_sizes, int n_in,
                              void* d_out, int out_size) {
    const float* x     = nullptr;
    const void*  batch = nullptr;
    const float* W     = nullptr;
    const float* b     = nullptr;
    const float* gamma = nullptr;
    const float* beta  = nullptr;

    for (int i = 0; i < n_in; i++) {
        int s = in_sizes[i];
        if (s == N_NODES * HIDDEN)         x = (const float*)d_in[i];
        else if (s == N_NODES)             batch = d_in[i];
        else if (s == 3 * HIDDEN * HIDDEN) W = (const float*)d_in[i];
        else if (s == HIDDEN) {
            if (!b) b = (const float*)d_in[i];
            else if (!gamma) gamma = (const float*)d_in[i];
            else if (!beta)  beta = (const float*)d_in[i];
        }
    }

    detect_kernel<<<1, 1>>>((const int2*)batch);
    {
        int total = N_GRAPHS * HIDDEN;
        int thr = 256;
        init_kernel<<<(total + thr - 1) / thr, thr>>>();
    }
    pool_kernel<<<POOL_BLOCKS, POOL_THREADS>>>((const float4*)x, batch);
    epilogue_kernel<<<N_GRAPHS / GPB, 128>>>(W, b, gamma, beta, (float*)d_out);
}

// round 4
// speedup vs baseline: 1.0905x; 1.0107x over previous
#include <cuda_runtime.h>
#include <cuda_bf16.h>
#include <cstdint>

// Problem constants (fixed-shape problem)
#define HIDDEN   128
#define N_NODES  1000000
#define N_GRAPHS 4096

#define ROWS_PER_WARP 64
#define N_WARPSPANS   (N_NODES / ROWS_PER_WARP)   // 15625 exactly
#define POOL_THREADS  256
#define POOL_BLOCKS   ((N_WARPSPANS + (POOL_THREADS/32) - 1) / (POOL_THREADS/32)) // 1954

// Scratch (no cudaMalloc allowed)
__device__ float    g_sums[N_GRAPHS * HIDDEN];
__device__ unsigned g_maxs[N_GRAPHS * HIDDEN];   // ordered-uint encoded floats
__device__ int      g_counts[N_GRAPHS];
__device__ int      g_is64;                      // batch dtype flag

// ---- ordered-uint float encoding (monotone; supports atomicMax) ----
__device__ __forceinline__ unsigned ordf(float f) {
    unsigned u = __float_as_uint(f);
    return (u & 0x80000000u) ? ~u : (u | 0x80000000u);
}
__device__ __forceinline__ float unordf(unsigned u) {
    return __uint_as_float((u & 0x80000000u) ? (u ^ 0x80000000u) : ~u);
}
#define ORD_NEG_INF 0x007FFFFFu

// ------------------------------------------------------------------
// Kernel 0: init scratch + detect batch dtype (merged).
// Sorted ids in [0,4096): int64 elements always have zero high words.
// ------------------------------------------------------------------
__global__ void init_kernel(const int2* __restrict__ b2) {
    int i = blockIdx.x * blockDim.x + threadIdx.x;
    if (i < N_GRAPHS * HIDDEN) {
        g_sums[i] = 0.0f;
        g_maxs[i] = ORD_NEG_INF;
    }
    if (i < N_GRAPHS) g_counts[i] = 0;
    if (i == 0) {
        int nonzero_hi = 0;
        #pragma unroll
        for (int k = 1; k <= 8; k++) {
            nonzero_hi |= b2[N_NODES / 2 - k].y;
            nonzero_hi |= b2[N_NODES / 4 + k].y;
        }
        g_is64 = (nonzero_hi == 0) ? 1 : 0;
    }
}

// ------------------------------------------------------------------
// Kernel 1: pooling. Per-warp contiguous 64-row span, register
// accumulation, atomic flush on segment boundaries only.
// (measured ~88% of HBM spec — at the roofline, unchanged)
// ------------------------------------------------------------------
__device__ __forceinline__ void flush_seg(int g, float4 a, float4 m, int n, int lane) {
    if ((unsigned)g >= N_GRAPHS) return;
    float*    sp = &g_sums[g * HIDDEN + 4 * lane];
    unsigned* mp = &g_maxs[g * HIDDEN + 4 * lane];
    atomicAdd(sp + 0, a.x);
    atomicAdd(sp + 1, a.y);
    atomicAdd(sp + 2, a.z);
    atomicAdd(sp + 3, a.w);
    atomicMax(mp + 0, ordf(m.x));
    atomicMax(mp + 1, ordf(m.y));
    atomicMax(mp + 2, ordf(m.z));
    atomicMax(mp + 3, ordf(m.w));
    if (lane == 0) atomicAdd(&g_counts[g], n);
}

template <typename IT>
__device__ __forceinline__ void pool_span(const float4* __restrict__ x4,
                                          const IT* __restrict__ batch,
                                          int row0, int lane) {
    const float NEG_INF = -__int_as_float(0x7F800000); // -inf
    float4 acc = make_float4(0.f, 0.f, 0.f, 0.f);
    float4 mx  = make_float4(NEG_INF, NEG_INF, NEG_INF, NEG_INF);
    int cur = -1, seglen = 0;

    for (int mb = 0; mb < ROWS_PER_WARP / 8; mb++) {
        int base = row0 + mb * 8;
        int    bb[8];
        float4 vv[8];
        #pragma unroll
        for (int i = 0; i < 8; i++) {
            bb[i] = (int)batch[base + i];
            vv[i] = __ldcs(&x4[(size_t)(base + i) * (HIDDEN / 4) + lane]);
        }
        #pragma unroll
        for (int i = 0; i < 8; i++) {
            int g = bb[i];
            if (g != cur) {
                if (cur >= 0) flush_seg(cur, acc, mx, seglen, lane);
                cur = g;
                acc = make_float4(0.f, 0.f, 0.f, 0.f);
                mx  = make_float4(NEG_INF, NEG_INF, NEG_INF, NEG_INF);
                seglen = 0;
            }
            acc.x += vv[i].x; acc.y += vv[i].y; acc.z += vv[i].z; acc.w += vv[i].w;
            mx.x = fmaxf(mx.x, vv[i].x); mx.y = fmaxf(mx.y, vv[i].y);
            mx.z = fmaxf(mx.z, vv[i].z); mx.w = fmaxf(mx.w, vv[i].w);
            seglen++;
        }
    }
    flush_seg(cur, acc, mx, seglen, lane);
}

__global__ __launch_bounds__(POOL_THREADS)
void pool_kernel(const float4* __restrict__ x4, const void* __restrict__ batch) {
    int wg   = (blockIdx.x * blockDim.x + threadIdx.x) >> 5;
    int lane = threadIdx.x & 31;
    if (wg >= N_WARPSPANS) return;
    int row0 = wg * ROWS_PER_WARP;

    if (g_is64) pool_span<long long>(x4, (const long long*)batch, row0, lane);
    else        pool_span<int>(x4, (const int*)batch, row0, lane);
}

// ------------------------------------------------------------------
// Kernel 2: epilogue, overlap-structured.
// 256 blocks x 256 threads (8 warps), GPB=16 graphs/block, warp owns
// 2 graphs, lane owns 4 output cols (as 2x f32x2).
// - Ps rows built per-warp (no block barrier)
// - W tiles (64x128) double-buffered: LDG prefetch of tile kt+1
//   overlaps compute of tile kt; one barrier per tile.
// Dynamic smem: 2x32KB W + 24KB Ps = 90KB -> 2 blocks/SM.
// ------------------------------------------------------------------
#define GPB 16
#define KT  64
#define W_TILE_F4 2048                 // KT*HIDDEN/4
#define SMEM_EPI  (2 * KT * HIDDEN * 4 + GPB * 384 * 4)   // 90112 B

__device__ __forceinline__ void ffma2(unsigned long long& acc,
                                      unsigned long long w2,
                                      unsigned long long p2) {
    asm("fma.rn.f32x2 %0, %1, %2, %0;" : "+l"(acc) : "l"(w2), "l"(p2));
}
__device__ __forceinline__ unsigned long long pack2(float p) {
    unsigned long long r;
    asm("mov.b64 %0, {%1, %1};" : "=l"(r) : "r"(__float_as_uint(p)));
    return r;
}

__global__ __launch_bounds__(256, 2)
void epilogue_kernel(const float* __restrict__ W, const float* __restrict__ bias,
                     const float* __restrict__ gamma, const float* __restrict__ beta,
                     float* __restrict__ out) {
    extern __shared__ float dynsmem[];
    float* Ws = dynsmem;                                    // [2][KT*HIDDEN]
    float (*Ps)[384] = (float(*)[384])(dynsmem + 2 * KT * HIDDEN);

    int g0   = blockIdx.x * GPB;
    int tid  = threadIdx.x;           // 256
    int warp = tid >> 5, lane = tid & 31;
    const float4* Wg = (const float4*)W;

    // ---- prefetch W tile 0 into registers ----
    float4 pf[8];
    #pragma unroll
    for (int i = 0; i < 8; i++) pf[i] = Wg[tid + i * 256];

    // ---- per-warp Ps build (2 graphs), warp-local only ----
    int glA = 2 * warp;
    #pragma unroll
    for (int g = 0; g < 2; g++) {
        int gg  = g0 + glA + g;
        int cnt = g_counts[gg];
        float inv = 1.0f / fmaxf((float)cnt, 1.0f);
        #pragma unroll
        for (int it = 0; it < 12; it++) {
            int col = it * 32 + lane;        // 0..383
            int sec = col >> 7;
            int c   = col & 127;
            float v;
            if (sec == 0)      v = g_sums[gg * HIDDEN + c] * inv;
            else if (sec == 1) v = (cnt > 0) ? unordf(g_maxs[gg * HIDDEN + c]) : 0.f;
            else               v = g_sums[gg * HIDDEN + c];
            Ps[glA + g][col] = v;
        }
    }
    __syncwarp();

    // ---- store tile 0, sync ----
    #pragma unroll
    for (int i = 0; i < 8; i++) ((float4*)Ws)[tid + i * 256] = pf[i];
    __syncthreads();

    unsigned long long acc2[2][2] = {{0ull,0ull},{0ull,0ull}};

    #pragma unroll 1
    for (int kt = 0; kt < 6; kt++) {
        const float* Wbuf = Ws + (kt & 1) * (KT * HIDDEN);

        // prefetch next tile (overlaps compute below)
        if (kt < 5) {
            const float4* Wn = Wg + (kt + 1) * W_TILE_F4;
            #pragma unroll
            for (int i = 0; i < 8; i++) pf[i] = Wn[tid + i * 256];
        }

        const float4* PsA = (const float4*)&Ps[glA][kt * KT];
        const float4* PsB = (const float4*)&Ps[glA + 1][kt * KT];

        #pragma unroll 4
        for (int k4 = 0; k4 < KT / 4; k4++) {
            float4 p0 = PsA[k4];     // broadcast LDS.128
            float4 p1 = PsB[k4];
            #pragma unroll
            for (int kk = 0; kk < 4; kk++) {
                int k = k4 * 4 + kk;
                ulonglong2 w2 = ((const ulonglong2*)(Wbuf + k * HIDDEN))[lane];
                float a = (kk == 0) ? p0.x : (kk == 1) ? p0.y : (kk == 2) ? p0.z : p0.w;
                float b = (kk == 0) ? p1.x : (kk == 1) ? p1.y : (kk == 2) ? p1.z : p1.w;
                unsigned long long pa = pack2(a), pb = pack2(b);
                ffma2(acc2[0][0], w2.x, pa);
                ffma2(acc2[0][1], w2.y, pa);
                ffma2(acc2[1][0], w2.x, pb);
                ffma2(acc2[1][1], w2.y, pb);
            }
        }

        if (kt < 5) {
            float4* Wd = (float4*)(Ws + ((kt + 1) & 1) * (KT * HIDDEN));
            #pragma unroll
            for (int i = 0; i < 8; i++) Wd[tid + i * 256] = pf[i];
            __syncthreads();
        }
    }

    // ---- bias + LayerNorm + exact GELU (2 graphs per warp) ----
    float4 b4 = ((const float4*)bias)[lane];
    float4 gm = ((const float4*)gamma)[lane];
    float4 bt = ((const float4*)beta)[lane];
    const float eps = 1e-5f;

    #pragma unroll
    for (int gi = 0; gi < 2; gi++) {
        int g = g0 + glA + gi;
        unsigned lo0, hi0, lo1, hi1;
        asm("mov.b64 {%0, %1}, %2;" : "=r"(lo0), "=r"(hi0) : "l"(acc2[gi][0]));
        asm("mov.b64 {%0, %1}, %2;" : "=r"(lo1), "=r"(hi1) : "l"(acc2[gi][1]));
        float h[4];
        h[0] = __uint_as_float(lo0) + b4.x;
        h[1] = __uint_as_float(hi0) + b4.y;
        h[2] = __uint_as_float(lo1) + b4.z;
        h[3] = __uint_as_float(hi1) + b4.w;

        float s = h[0] + h[1] + h[2] + h[3];
        #pragma unroll
        for (int o = 16; o; o >>= 1) s += __shfl_xor_sync(0xFFFFFFFFu, s, o);
        float mu = s * (1.0f / 128.0f);

        float d0 = h[0]-mu, d1 = h[1]-mu, d2 = h[2]-mu, d3 = h[3]-mu;
        float v = d0*d0 + d1*d1 + d2*d2 + d3*d3;
        #pragma unroll
        for (int o = 16; o; o >>= 1) v += __shfl_xor_sync(0xFFFFFFFFu, v, o);
        float rstd = rsqrtf(v * (1.0f / 128.0f) + eps);

        float gmv[4] = {gm.x, gm.y, gm.z, gm.w};
        float btv[4] = {bt.x, bt.y, bt.z, bt.w};
        #pragma unroll
        for (int k = 0; k < 4; k++) {
            float t = (h[k] - mu) * rstd * gmv[k] + btv[k];
            float ge = 0.5f * t * (1.0f + erff(t * 0.70710678118654752f));
            out[(size_t)g * HIDDEN + 4 * lane + k] = ge;
        }
    }
}

// ------------------------------------------------------------------
extern "C" void kernel_launch(void* const* d_in, const int* in_sizes, int n_in,
                              void* d_out, int out_size) {
    const float* x     = nullptr;
    const void*  batch = nullptr;
    const float* W     = nullptr;
    const float* b     = nullptr;
    const float* gamma = nullptr;
    const float* beta  = nullptr;

    for (int i = 0; i < n_in; i++) {
        int s = in_sizes[i];
        if (s == N_NODES * HIDDEN)         x = (const float*)d_in[i];
        else if (s == N_NODES)             batch = d_in[i];
        else if (s == 3 * HIDDEN * HIDDEN) W = (const float*)d_in[i];
        else if (s == HIDDEN) {
            if (!b) b = (const float*)d_in[i];
            else if (!gamma) gamma = (const float*)d_in[i];
            else if (!beta)  beta = (const float*)d_in[i];
        }
    }

    // allow 90KB dynamic smem for the epilogue (host attr, not an alloc)
    cudaFuncSetAttribute(epilogue_kernel,
                         cudaFuncAttributeMaxDynamicSharedMemorySize, SMEM_EPI);

    {
        int total = N_GRAPHS * HIDDEN;
        int thr = 256;
        init_kernel<<<(total + thr - 1) / thr, thr>>>((const int2*)batch);
    }
    pool_kernel<<<POOL_BLOCKS, POOL_THREADS>>>((const float4*)x, batch);
    epilogue_kernel<<<N_GRAPHS / GPB, 256, SMEM_EPI>>>(W, b, gamma, beta, (float*)d_out);
}